// round 11
// baseline (speedup 1.0000x reference)
#include <cuda_runtime.h>
#include <cuda_fp16.h>
#include <math.h>
#include <cstdint>

#define N_NODES 50000
#define F       128
#define NCLS    2
#define N_TILES ((N_NODES + 127) / 128)   // 391
#define BUCKET  64                         // slots per node (Poisson(16) safe)

// Scratch (device globals: allocation-free; zero-initialized at load)
__device__ __half g_feat16[N_NODES * F];          // 12.8 MB
__device__ int    g_cnt[N_NODES];                 // zeroed by fused kernel tail
__device__ int    g_bucket[N_NODES * BUCKET];     // 12.8 MB

// ---------------------------------------------------------------------------
// 0) prep+fill: convert feat->fp16, probe idx dtype, bucket-append edges
// ---------------------------------------------------------------------------
__global__ void prep_fill_kernel(const float* __restrict__ feat,
                                 const void* __restrict__ srcv,
                                 const void* __restrict__ dstv, int E) {
    __shared__ int s_nz;
    int tid = threadIdx.x;
    if (tid == 0) s_nz = 0;
    __syncthreads();
    if (tid < 64) {                        // per-block dtype probe (L2-cached)
        const int* s32 = (const int*)srcv;
        const int* d32 = (const int*)dstv;
        int lim = 2 * E < 128 ? 2 * E : 128;
        int i = 2 * tid + 1;
        if (i < lim && (s32[i] | d32[i])) atomicOr(&s_nz, 1);
    }
    __syncthreads();
    const int is64 = (s_nz == 0);          // all odd 32b words zero => int64

    int gtid = blockIdx.x * blockDim.x + tid;
    int stride = gridDim.x * blockDim.x;

    // edges: count + bucket append
    for (int i = gtid; i < E; i += stride) {
        int d, s;
        if (is64) {
            d = (int)reinterpret_cast<const long long*>(dstv)[i];
            s = (int)reinterpret_cast<const long long*>(srcv)[i];
        } else {
            d = reinterpret_cast<const int*>(dstv)[i];
            s = reinterpret_cast<const int*>(srcv)[i];
        }
        if (d < 0 || d >= N_NODES || s < 0 || s >= N_NODES) continue;
        int pos = atomicAdd(&g_cnt[d], 1);
        if (pos < BUCKET) g_bucket[(size_t)d * BUCKET + pos] = s;
    }

    // feat -> fp16
    const int NH4 = N_NODES * F / 4;
    const float4* f4 = (const float4*)feat;
    uint2* o2 = (uint2*)g_feat16;
    for (int i = gtid; i < NH4; i += stride) {
        float4 v = f4[i];
        __half2 h0 = __float22half2_rn(make_float2(v.x, v.y));
        __half2 h1 = __float22half2_rn(make_float2(v.z, v.w));
        uint2 o;
        o.x = *(uint32_t*)&h0;
        o.y = *(uint32_t*)&h1;
        o2[i] = o;
    }
}

// ---------------------------------------------------------------------------
// 1) fused aggregate + fp16 mma GEMM (persistent, 148 CTAs x 512 thr):
//    per tile: cp.async feat half of A, gather-mean agg half directly into
//    A-tile smem, ldmatrix+mma, fused bias/relu/fc/sigmoid epilogue.
// ---------------------------------------------------------------------------
#define RSTRIDE  528    // bytes per smem A/B row (256 halves + 16B pad)
#define RWORDS   132    // u32 per row
#define A_BUF    67584  // 128 rows * 528 B
#define OFF_B    0
#define OFF_A    67584                    // 2 bufs -> ends 202752
#define OFF_BN   202752
#define OFF_F0   203264
#define OFF_F1   203776
#define OFF_PART 204288                   // [128][4][2] f32 = 4096 B
#define SMEM_TOTAL 208384

__device__ __forceinline__ uint32_t smem_u32(const void* p) {
    uint32_t a;
    asm("{ .reg .u64 t; cvta.to.shared.u64 t, %1; cvt.u32.u64 %0, t; }"
        : "=r"(a) : "l"(p));
    return a;
}
__device__ __forceinline__ void mma_f16(float* c, const uint32_t* a,
                                        const uint32_t* b) {
    asm volatile("mma.sync.aligned.m16n8k16.row.col.f32.f16.f16.f32 "
                 "{%0,%1,%2,%3}, {%4,%5,%6,%7}, {%8,%9}, {%0,%1,%2,%3};"
                 : "+f"(c[0]), "+f"(c[1]), "+f"(c[2]), "+f"(c[3])
                 : "r"(a[0]), "r"(a[1]), "r"(a[2]), "r"(a[3]),
                   "r"(b[0]), "r"(b[1]));
}
#define LDSM4(r, addr) \
    asm volatile("ldmatrix.sync.aligned.m8n8.x4.shared.b16 {%0,%1,%2,%3}, [%4];" \
                 : "=r"((r)[0]), "=r"((r)[1]), "=r"((r)[2]), "=r"((r)[3]) \
                 : "r"(addr))
#define CP_ASYNC16(dst, src) \
    asm volatile("cp.async.cg.shared.global [%0], [%1], 16;" \
                 :: "r"(dst), "l"(src) : "memory")
#define CP_COMMIT() asm volatile("cp.async.commit_group;" ::: "memory")
#define CP_WAIT0()  asm volatile("cp.async.wait_group 0;" ::: "memory")

__global__ void __launch_bounds__(512, 1)
fused_gemm_kernel(const float* __restrict__ Wself,
                  const float* __restrict__ Wneigh,
                  const float* __restrict__ bneigh,
                  const float* __restrict__ Wfc,
                  const float* __restrict__ bfc,
                  float* __restrict__ out) {
    extern __shared__ char smem[];
    uint32_t* Bs = (uint32_t*)(smem + OFF_B);    // [n=128][k2=128]+pad
    float* bn_s  = (float*)(smem + OFF_BN);
    float* f0_s  = (float*)(smem + OFF_F0);
    float* f1_s  = (float*)(smem + OFF_F1);
    float* part  = (float*)(smem + OFF_PART);
    const uint32_t sbase = smem_u32(smem);
    const uint32_t sA = sbase + OFF_A;
    const uint32_t sB = sbase + OFF_B;

    const int tid = threadIdx.x;
    const int wid = tid >> 5, lane = tid & 31;
    const int m_idx = wid >> 2;          // 0..3: rows m_idx*32..+32
    const int n_idx = wid & 3;           // 0..3: cols n_idx*32..+32
    const int groupr = lane >> 2, tcol = lane & 3;

    // --- stage B = [Ws | Wn] as [n][k] fp16, once per CTA -------------------
    const float4* Ws4 = (const float4*)Wself;
    const float4* Wn4 = (const float4*)Wneigh;
    for (int t = tid; t < 128 * 64; t += 512) {
        int j  = t >> 6;                  // output col n (row of B)
        int kq = t & 63;                  // float4 index along combined K(256)
        float4 v = (kq < 32) ? Ws4[j * 32 + kq] : Wn4[j * 32 + (kq - 32)];
        __half2 h0 = __float22half2_rn(make_float2(v.x, v.y));
        __half2 h1 = __float22half2_rn(make_float2(v.z, v.w));
        uint2 o;
        o.x = *(uint32_t*)&h0;
        o.y = *(uint32_t*)&h1;
        *(uint2*)&Bs[j * RWORDS + kq * 2] = o;
    }
    if (tid < 128) {
        bn_s[tid] = bneigh[tid];
        f0_s[tid] = Wfc[tid];
        f1_s[tid] = Wfc[128 + tid];
    }

    const char* featb = (const char*)g_feat16;
    const float bfc0 = bfc[0], bfc1 = bfc[1];

    // ldmatrix lane address components (bytes)
    const uint32_t aOff = (uint32_t)((m_idx * 32 + (lane & 15)) * RSTRIDE +
                                     (lane >> 4) * 16);
    const uint32_t bAddr0 = sB + (uint32_t)((n_idx * 32 + (lane & 7) +
                                             ((lane >> 4) & 1) * 8) * RSTRIDE +
                                            ((lane >> 3) & 1) * 16);

    // feat half of A tile: 128 rows x 256 B via cp.async (one commit group)
    auto stageF = [&](int tile, int bufi) {
        #pragma unroll
        for (int i = 0; i < 4; i++) {
            int idx = tid + i * 512;              // 0..2047
            int row = idx >> 4, q = idx & 15;     // 16 x 16B segs per row
            int node = tile * 128 + row;
            if (node >= N_NODES) node = N_NODES - 1;
            const char* src = featb + (size_t)node * 256 + q * 16;
            uint32_t dst = sA + bufi * A_BUF + row * RSTRIDE + q * 16;
            CP_ASYNC16(dst, src);
        }
        CP_COMMIT();
    };

    // agg half of A tile: each warp gathers+means 8 node rows into smem
    const uint2* f2 = (const uint2*)g_feat16;     // 32 uint2 per row
    auto gather = [&](int tile, int bufi) {
        #pragma unroll 1
        for (int r = 0; r < 8; r++) {
            int row = wid * 8 + r;
            int node = tile * 128 + row;
            bool real = (node < N_NODES);
            int nc = real ? node : N_NODES - 1;
            int deg = g_cnt[nc];
            int n = deg < BUCKET ? deg : BUCKET;
            const int* bk = &g_bucket[(size_t)nc * BUCKET];
            float a0 = 0.f, a1 = 0.f, a2 = 0.f, a3 = 0.f;
            int e = 0;
            for (; e + 1 < n; e += 2) {
                int s0 = bk[e], s1 = bk[e + 1];
                uint2 u0 = f2[(size_t)s0 * 32 + lane];
                uint2 u1 = f2[(size_t)s1 * 32 + lane];
                float2 p0 = __half22float2(*(__half2*)&u0.x);
                float2 p1 = __half22float2(*(__half2*)&u0.y);
                float2 q0 = __half22float2(*(__half2*)&u1.x);
                float2 q1 = __half22float2(*(__half2*)&u1.y);
                a0 += p0.x + q0.x; a1 += p0.y + q0.y;
                a2 += p1.x + q1.x; a3 += p1.y + q1.y;
            }
            if (e < n) {
                int s0 = bk[e];
                uint2 u0 = f2[(size_t)s0 * 32 + lane];
                float2 p0 = __half22float2(*(__half2*)&u0.x);
                float2 p1 = __half22float2(*(__half2*)&u0.y);
                a0 += p0.x; a1 += p0.y; a2 += p1.x; a3 += p1.y;
            }
            float invd = __fdividef(1.0f, fmaxf((float)deg, 1.0f));
            __half2 h0 = __float22half2_rn(make_float2(a0 * invd, a1 * invd));
            __half2 h1 = __float22half2_rn(make_float2(a2 * invd, a3 * invd));
            uint2 o;
            o.x = *(uint32_t*)&h0;
            o.y = *(uint32_t*)&h1;
            *(uint2*)(smem + OFF_A + bufi * A_BUF + row * RSTRIDE + 256 +
                      lane * 8) = o;
            if (real && lane == 0) g_cnt[nc] = 0;   // invariant for next call
        }
    };

    int buf = 0;
    int tile0 = blockIdx.x;
    if (tile0 < N_TILES) { stageF(tile0, 0); gather(tile0, 0); }

    for (int tile = tile0; tile < N_TILES; tile += gridDim.x) {
        CP_WAIT0();
        __syncthreads();                  // A tile (feat cp + gather STS) ready

        float C[2][4][4];
        #pragma unroll
        for (int mt = 0; mt < 2; mt++)
            #pragma unroll
            for (int nt = 0; nt < 4; nt++)
                #pragma unroll
                for (int i = 0; i < 4; i++) C[mt][nt][i] = 0.f;

        const uint32_t aBase = sA + buf * A_BUF + aOff;
        #pragma unroll
        for (int k = 0; k < 16; k++) {    // 16 k-steps of 16 halves
            uint32_t a0[4], a1[4], b0[4], b1[4];
            LDSM4(a0, aBase + k * 32);
            LDSM4(a1, aBase + 16 * RSTRIDE + k * 32);
            LDSM4(b0, bAddr0 + k * 32);
            LDSM4(b1, bAddr0 + 16 * RSTRIDE + k * 32);
            mma_f16(C[0][0], a0, b0);
            mma_f16(C[0][1], a0, b0 + 2);
            mma_f16(C[0][2], a0, b1);
            mma_f16(C[0][3], a0, b1 + 2);
            mma_f16(C[1][0], a1, b0);
            mma_f16(C[1][1], a1, b0 + 2);
            mma_f16(C[1][2], a1, b1);
            mma_f16(C[1][3], a1, b1 + 2);
        }
        __syncthreads();                  // all warps done reading buf

        int next = tile + gridDim.x;
        if (next < N_TILES) stageF(next, buf ^ 1);   // overlap with epilogue

        // --- epilogue: h = relu(c + bn); p += h * fc; quad-reduce ----------
        float p[2][2][2];   // [mt][rowhalf][cls]
        #pragma unroll
        for (int mt = 0; mt < 2; mt++)
            #pragma unroll
            for (int hh = 0; hh < 2; hh++) { p[mt][hh][0] = 0.f; p[mt][hh][1] = 0.f; }

        #pragma unroll
        for (int nt = 0; nt < 4; nt++) {
            #pragma unroll
            for (int ii = 0; ii < 2; ii++) {
                int col = n_idx * 32 + nt * 8 + 2 * tcol + ii;
                float bnv = bn_s[col], f0v = f0_s[col], f1v = f1_s[col];
                #pragma unroll
                for (int mt = 0; mt < 2; mt++) {
                    #pragma unroll
                    for (int hh = 0; hh < 2; hh++) {
                        float h = fmaxf(C[mt][nt][hh * 2 + ii] + bnv, 0.f);
                        p[mt][hh][0] += h * f0v;
                        p[mt][hh][1] += h * f1v;
                    }
                }
            }
        }
        #pragma unroll
        for (int mt = 0; mt < 2; mt++)
            #pragma unroll
            for (int hh = 0; hh < 2; hh++)
                #pragma unroll
                for (int cl = 0; cl < 2; cl++) {
                    float v = p[mt][hh][cl];
                    v += __shfl_xor_sync(0xffffffffu, v, 1);
                    v += __shfl_xor_sync(0xffffffffu, v, 2);
                    p[mt][hh][cl] = v;
                }
        if (tcol == 0) {
            #pragma unroll
            for (int mt = 0; mt < 2; mt++)
                #pragma unroll
                for (int hh = 0; hh < 2; hh++) {
                    int row = m_idx * 32 + mt * 16 + hh * 8 + groupr;
                    part[row * 8 + n_idx * 2 + 0] = p[mt][hh][0];
                    part[row * 8 + n_idx * 2 + 1] = p[mt][hh][1];
                }
        }
        __syncthreads();
        if (tid < 128) {
            int node = tile * 128 + tid;
            if (node < N_NODES) {
                float l0 = part[tid * 8 + 0] + part[tid * 8 + 2] +
                           part[tid * 8 + 4] + part[tid * 8 + 6] + bfc0;
                float l1 = part[tid * 8 + 1] + part[tid * 8 + 3] +
                           part[tid * 8 + 5] + part[tid * 8 + 7] + bfc1;
                float2 o;
                o.x = 1.0f / (1.0f + expf(-l0));
                o.y = 1.0f / (1.0f + expf(-l1));
                *(float2*)&out[(size_t)node * 2] = o;
            }
        }

        if (next < N_TILES) gather(next, buf ^ 1);   // overlap tail of tile

        buf ^= 1;
        // next iteration's post-MMA __syncthreads orders part/buf reuse
    }
}

// ---------------------------------------------------------------------------
extern "C" void kernel_launch(void* const* d_in, const int* in_sizes, int n_in,
                              void* d_out, int out_size) {
    const float* feat   = (const float*)d_in[0];
    const void*  src    = d_in[1];
    const void*  dst    = d_in[2];
    const float* Wself  = (const float*)d_in[3];
    const float* Wneigh = (const float*)d_in[4];
    const float* bneigh = (const float*)d_in[5];
    const float* Wfc    = (const float*)d_in[6];
    const float* bfc    = (const float*)d_in[7];
    float*       out    = (float*)d_out;
    int E = in_sizes[1];

    cudaFuncSetAttribute(fused_gemm_kernel,
                         cudaFuncAttributeMaxDynamicSharedMemorySize, SMEM_TOTAL);

    prep_fill_kernel<<<1024, 256>>>(feat, src, dst, E);
    fused_gemm_kernel<<<148, 512, SMEM_TOTAL>>>(
        Wself, Wneigh, bneigh, Wfc, bfc, out);
}

// round 12
// speedup vs baseline: 1.8269x; 1.8269x over previous
#include <cuda_runtime.h>
#include <cuda_fp16.h>
#include <math.h>
#include <cstdint>

#define N_NODES 50000
#define F       128
#define NCLS    2
#define N_TILES ((N_NODES + 127) / 128)   // 391
#define BUCKET  64                         // slots per node (Poisson(16) safe)

// Scratch (device globals: allocation-free; zero-initialized at load)
__device__ __half g_feat16[N_NODES * F];          // 12.8 MB
__device__ __half g_agg16[N_NODES * F];           // 12.8 MB (mean, scaled)
__device__ int    g_cnt[N_NODES];                 // zeroed by aggregate tail
__device__ int    g_bucket[N_NODES * BUCKET];     // 12.8 MB

// ---------------------------------------------------------------------------
// 0) prep+fill: convert feat->fp16, probe idx dtype, bucket-append edges
//    (4 edges/thread, vector index loads for MLP)
// ---------------------------------------------------------------------------
__global__ void prep_fill_kernel(const float* __restrict__ feat,
                                 const void* __restrict__ srcv,
                                 const void* __restrict__ dstv, int E) {
    __shared__ int s_nz;
    int tid = threadIdx.x;
    if (tid == 0) s_nz = 0;
    __syncthreads();
    if (tid < 64) {                        // per-block dtype probe (L2-cached)
        const int* s32 = (const int*)srcv;
        const int* d32 = (const int*)dstv;
        int lim = 2 * E < 128 ? 2 * E : 128;
        int i = 2 * tid + 1;
        if (i < lim && (s32[i] | d32[i])) atomicOr(&s_nz, 1);
    }
    __syncthreads();
    const int is64 = (s_nz == 0);          // all odd 32b words zero => int64

    int gtid = blockIdx.x * blockDim.x + tid;
    int stride = gridDim.x * blockDim.x;

    // edges: 4 per thread, batched loads -> batched atomics -> batched stores
    int nquad = (E + 3) >> 2;
    for (int qi = gtid; qi < nquad; qi += stride) {
        int base = qi * 4;
        int d[4], s[4];
        int cnt4 = (E - base) < 4 ? (E - base) : 4;
        if (cnt4 == 4) {
            if (is64) {
                const longlong2* dp = (const longlong2*)((const long long*)dstv + base);
                const longlong2* sp = (const longlong2*)((const long long*)srcv + base);
                longlong2 d01 = dp[0], d23 = dp[1];
                longlong2 s01 = sp[0], s23 = sp[1];
                d[0] = (int)d01.x; d[1] = (int)d01.y;
                d[2] = (int)d23.x; d[3] = (int)d23.y;
                s[0] = (int)s01.x; s[1] = (int)s01.y;
                s[2] = (int)s23.x; s[3] = (int)s23.y;
            } else {
                int4 dv = *(const int4*)((const int*)dstv + base);
                int4 sv = *(const int4*)((const int*)srcv + base);
                d[0] = dv.x; d[1] = dv.y; d[2] = dv.z; d[3] = dv.w;
                s[0] = sv.x; s[1] = sv.y; s[2] = sv.z; s[3] = sv.w;
            }
        } else {
            for (int j = 0; j < 4; j++) {
                if (j < cnt4) {
                    if (is64) {
                        d[j] = (int)reinterpret_cast<const long long*>(dstv)[base + j];
                        s[j] = (int)reinterpret_cast<const long long*>(srcv)[base + j];
                    } else {
                        d[j] = reinterpret_cast<const int*>(dstv)[base + j];
                        s[j] = reinterpret_cast<const int*>(srcv)[base + j];
                    }
                } else { d[j] = -1; s[j] = -1; }
            }
        }
        int pos[4];
        #pragma unroll
        for (int j = 0; j < 4; j++) {
            bool ok = (d[j] >= 0 && d[j] < N_NODES && s[j] >= 0 && s[j] < N_NODES);
            pos[j] = ok ? atomicAdd(&g_cnt[d[j]], 1) : BUCKET;
        }
        #pragma unroll
        for (int j = 0; j < 4; j++) {
            if (pos[j] < BUCKET)
                g_bucket[(size_t)d[j] * BUCKET + pos[j]] = s[j];
        }
    }

    // feat -> fp16
    const int NH4 = N_NODES * F / 4;
    const float4* f4 = (const float4*)feat;
    uint2* o2 = (uint2*)g_feat16;
    for (int i = gtid; i < NH4; i += stride) {
        float4 v = f4[i];
        __half2 h0 = __float22half2_rn(make_float2(v.x, v.y));
        __half2 h1 = __float22half2_rn(make_float2(v.z, v.w));
        uint2 o;
        o.x = *(uint32_t*)&h0;
        o.y = *(uint32_t*)&h1;
        o2[i] = o;
    }
}

// ---------------------------------------------------------------------------
// 1) aggregate: warp per node, fp16 gather, f32 accumulate, fp16 store;
//    zeroes g_cnt afterwards (invariant for next launch/graph replay)
// ---------------------------------------------------------------------------
__global__ void __launch_bounds__(256)
aggregate_kernel() {
    int warp = (blockIdx.x * blockDim.x + threadIdx.x) >> 5;
    int lane = threadIdx.x & 31;
    if (warp >= N_NODES) return;
    int deg = g_cnt[warp];
    int n = deg < BUCKET ? deg : BUCKET;
    const int* bk = &g_bucket[(size_t)warp * BUCKET];

    const uint2* f2 = (const uint2*)g_feat16;   // 32 uint2 per row (4 halves)
    float a0 = 0.f, a1 = 0.f, a2 = 0.f, a3 = 0.f;
    int e = 0;
    for (; e + 1 < n; e += 2) {
        int s0 = bk[e], s1 = bk[e + 1];
        uint2 u0 = f2[(size_t)s0 * 32 + lane];
        uint2 u1 = f2[(size_t)s1 * 32 + lane];
        float2 p0 = __half22float2(*(__half2*)&u0.x);
        float2 p1 = __half22float2(*(__half2*)&u0.y);
        float2 q0 = __half22float2(*(__half2*)&u1.x);
        float2 q1 = __half22float2(*(__half2*)&u1.y);
        a0 += p0.x + q0.x; a1 += p0.y + q0.y;
        a2 += p1.x + q1.x; a3 += p1.y + q1.y;
    }
    if (e < n) {
        int s0 = bk[e];
        uint2 u0 = f2[(size_t)s0 * 32 + lane];
        float2 p0 = __half22float2(*(__half2*)&u0.x);
        float2 p1 = __half22float2(*(__half2*)&u0.y);
        a0 += p0.x; a1 += p0.y; a2 += p1.x; a3 += p1.y;
    }
    float invd = __fdividef(1.0f, fmaxf((float)deg, 1.0f));
    __half2 h0 = __float22half2_rn(make_float2(a0 * invd, a1 * invd));
    __half2 h1 = __float22half2_rn(make_float2(a2 * invd, a3 * invd));
    uint2 o;
    o.x = *(uint32_t*)&h0;
    o.y = *(uint32_t*)&h1;
    ((uint2*)g_agg16)[(size_t)warp * 32 + lane] = o;
    if (lane == 0) g_cnt[warp] = 0;       // restore invariant for next call
}

// ---------------------------------------------------------------------------
// 2) fp16 mma GEMM with ldmatrix fragments, one barrier per tile,
//    whole-tile cp.async double buffer, fused bias/relu/fc/sigmoid epilogue
// ---------------------------------------------------------------------------
#define RSTRIDE  528    // bytes per smem row (256 halves + 16B pad)
#define RWORDS   132    // u32 per row
#define A_BUF    67584  // 128 rows * 528 B
#define OFF_B    0
#define OFF_A    67584                    // 2 bufs -> 135168
#define OFF_BN   202752
#define OFF_F0   203264
#define OFF_F1   203776
#define OFF_PART 204288                   // [128][4][2] f32 = 4096 B
#define SMEM_TOTAL 208384

__device__ __forceinline__ uint32_t smem_u32(const void* p) {
    uint32_t a;
    asm("{ .reg .u64 t; cvta.to.shared.u64 t, %1; cvt.u32.u64 %0, t; }"
        : "=r"(a) : "l"(p));
    return a;
}
__device__ __forceinline__ void mma_f16(float* c, const uint32_t* a,
                                        const uint32_t* b) {
    asm volatile("mma.sync.aligned.m16n8k16.row.col.f32.f16.f16.f32 "
                 "{%0,%1,%2,%3}, {%4,%5,%6,%7}, {%8,%9}, {%0,%1,%2,%3};"
                 : "+f"(c[0]), "+f"(c[1]), "+f"(c[2]), "+f"(c[3])
                 : "r"(a[0]), "r"(a[1]), "r"(a[2]), "r"(a[3]),
                   "r"(b[0]), "r"(b[1]));
}
#define LDSM4(r, addr) \
    asm volatile("ldmatrix.sync.aligned.m8n8.x4.shared.b16 {%0,%1,%2,%3}, [%4];" \
                 : "=r"((r)[0]), "=r"((r)[1]), "=r"((r)[2]), "=r"((r)[3]) \
                 : "r"(addr))
#define CP_ASYNC16(dst, src) \
    asm volatile("cp.async.cg.shared.global [%0], [%1], 16;" \
                 :: "r"(dst), "l"(src) : "memory")
#define CP_COMMIT() asm volatile("cp.async.commit_group;" ::: "memory")
#define CP_WAIT0()  asm volatile("cp.async.wait_group 0;" ::: "memory")

__global__ void __launch_bounds__(512, 1)
mma_gemm_kernel(const float* __restrict__ Wself,
                const float* __restrict__ Wneigh,
                const float* __restrict__ bneigh,
                const float* __restrict__ Wfc,
                const float* __restrict__ bfc,
                float* __restrict__ out) {
    extern __shared__ char smem[];
    uint32_t* Bs = (uint32_t*)(smem + OFF_B);    // [n=128][k2=128]+pad
    float* bn_s  = (float*)(smem + OFF_BN);
    float* f0_s  = (float*)(smem + OFF_F0);
    float* f1_s  = (float*)(smem + OFF_F1);
    float* part  = (float*)(smem + OFF_PART);
    const uint32_t sbase = smem_u32(smem);
    const uint32_t sA = sbase + OFF_A;
    const uint32_t sB = sbase + OFF_B;

    const int tid = threadIdx.x;
    const int wid = tid >> 5, lane = tid & 31;
    const int m_idx = wid >> 2;          // 0..3: rows m_idx*32..+32
    const int n_idx = wid & 3;           // 0..3: cols n_idx*32..+32
    const int groupr = lane >> 2, tcol = lane & 3;

    // --- stage B = [Ws | Wn] as [n][k] fp16, once per CTA -------------------
    const float4* Ws4 = (const float4*)Wself;
    const float4* Wn4 = (const float4*)Wneigh;
    for (int t = tid; t < 128 * 64; t += 512) {
        int j  = t >> 6;                  // output col n (row of B)
        int kq = t & 63;                  // float4 index along combined K(256)
        float4 v = (kq < 32) ? Ws4[j * 32 + kq] : Wn4[j * 32 + (kq - 32)];
        __half2 h0 = __float22half2_rn(make_float2(v.x, v.y));
        __half2 h1 = __float22half2_rn(make_float2(v.z, v.w));
        uint2 o;
        o.x = *(uint32_t*)&h0;
        o.y = *(uint32_t*)&h1;
        *(uint2*)&Bs[j * RWORDS + kq * 2] = o;
    }
    if (tid < 128) {
        bn_s[tid] = bneigh[tid];
        f0_s[tid] = Wfc[tid];
        f1_s[tid] = Wfc[128 + tid];
    }

    const char* featb = (const char*)g_feat16;
    const char* aggb  = (const char*)g_agg16;
    const float bfc0 = bfc[0], bfc1 = bfc[1];

    // ldmatrix lane address components (bytes)
    const uint32_t aOff = (uint32_t)((m_idx * 32 + (lane & 15)) * RSTRIDE +
                                     (lane >> 4) * 16);
    const uint32_t bAddr0 = sB + (uint32_t)((n_idx * 32 + (lane & 7) +
                                             ((lane >> 4) & 1) * 8) * RSTRIDE +
                                            ((lane >> 3) & 1) * 16);

    // whole-tile A stager: 128 rows x 512 B (feat | agg), one commit group
    auto stage = [&](int tile, int bufi) {
        #pragma unroll
        for (int i = 0; i < 8; i++) {
            int idx = tid + i * 512;              // 0..4095
            int row = idx >> 5, q = idx & 31;     // 32 x 16B segs per row
            int node = tile * 128 + row;
            if (node >= N_NODES) node = N_NODES - 1;
            const char* src = (q < 16)
                ? featb + (size_t)node * 256 + q * 16
                : aggb  + (size_t)node * 256 + (q - 16) * 16;
            uint32_t dst = sA + bufi * A_BUF + row * RSTRIDE + q * 16;
            CP_ASYNC16(dst, src);
        }
        CP_COMMIT();
    };

    int buf = 0;
    int tile0 = blockIdx.x;
    if (tile0 < N_TILES) stage(tile0, 0);

    for (int tile = tile0; tile < N_TILES; tile += gridDim.x) {
        CP_WAIT0();
        __syncthreads();                  // A tile ready for all warps

        float C[2][4][4];
        #pragma unroll
        for (int mt = 0; mt < 2; mt++)
            #pragma unroll
            for (int nt = 0; nt < 4; nt++)
                #pragma unroll
                for (int i = 0; i < 4; i++) C[mt][nt][i] = 0.f;

        const uint32_t aBase = sA + buf * A_BUF + aOff;
        #pragma unroll
        for (int k = 0; k < 16; k++) {    // 16 k-steps of 16 halves
            uint32_t a0[4], a1[4], b0[4], b1[4];
            LDSM4(a0, aBase + k * 32);
            LDSM4(a1, aBase + 16 * RSTRIDE + k * 32);
            LDSM4(b0, bAddr0 + k * 32);
            LDSM4(b1, bAddr0 + 16 * RSTRIDE + k * 32);
            mma_f16(C[0][0], a0, b0);
            mma_f16(C[0][1], a0, b0 + 2);
            mma_f16(C[0][2], a0, b1);
            mma_f16(C[0][3], a0, b1 + 2);
            mma_f16(C[1][0], a1, b0);
            mma_f16(C[1][1], a1, b0 + 2);
            mma_f16(C[1][2], a1, b1);
            mma_f16(C[1][3], a1, b1 + 2);
        }
        __syncthreads();                  // all warps done reading buf

        int next = tile + gridDim.x;      // prefetch overlaps epilogue
        if (next < N_TILES) stage(next, buf ^ 1);

        // --- epilogue: h = relu(c + bn); p += h * fc; quad-reduce ----------
        float p[2][2][2];   // [mt][rowhalf][cls]
        #pragma unroll
        for (int mt = 0; mt < 2; mt++)
            #pragma unroll
            for (int hh = 0; hh < 2; hh++) { p[mt][hh][0] = 0.f; p[mt][hh][1] = 0.f; }

        #pragma unroll
        for (int nt = 0; nt < 4; nt++) {
            #pragma unroll
            for (int ii = 0; ii < 2; ii++) {
                int col = n_idx * 32 + nt * 8 + 2 * tcol + ii;
                float bnv = bn_s[col], f0v = f0_s[col], f1v = f1_s[col];
                #pragma unroll
                for (int mt = 0; mt < 2; mt++) {
                    #pragma unroll
                    for (int hh = 0; hh < 2; hh++) {
                        float h = fmaxf(C[mt][nt][hh * 2 + ii] + bnv, 0.f);
                        p[mt][hh][0] += h * f0v;
                        p[mt][hh][1] += h * f1v;
                    }
                }
            }
        }
        #pragma unroll
        for (int mt = 0; mt < 2; mt++)
            #pragma unroll
            for (int hh = 0; hh < 2; hh++)
                #pragma unroll
                for (int cl = 0; cl < 2; cl++) {
                    float v = p[mt][hh][cl];
                    v += __shfl_xor_sync(0xffffffffu, v, 1);
                    v += __shfl_xor_sync(0xffffffffu, v, 2);
                    p[mt][hh][cl] = v;
                }
        if (tcol == 0) {
            #pragma unroll
            for (int mt = 0; mt < 2; mt++)
                #pragma unroll
                for (int hh = 0; hh < 2; hh++) {
                    int row = m_idx * 32 + mt * 16 + hh * 8 + groupr;
                    part[row * 8 + n_idx * 2 + 0] = p[mt][hh][0];
                    part[row * 8 + n_idx * 2 + 1] = p[mt][hh][1];
                }
        }
        __syncthreads();
        if (tid < 128) {
            int node = tile * 128 + tid;
            if (node < N_NODES) {
                float l0 = part[tid * 8 + 0] + part[tid * 8 + 2] +
                           part[tid * 8 + 4] + part[tid * 8 + 6] + bfc0;
                float l1 = part[tid * 8 + 1] + part[tid * 8 + 3] +
                           part[tid * 8 + 5] + part[tid * 8 + 7] + bfc1;
                float2 o;
                o.x = 1.0f / (1.0f + expf(-l0));
                o.y = 1.0f / (1.0f + expf(-l1));
                *(float2*)&out[(size_t)node * 2] = o;
            }
        }
        buf ^= 1;
        // next tile's post-MMA __syncthreads orders part reuse
    }
}

// ---------------------------------------------------------------------------
extern "C" void kernel_launch(void* const* d_in, const int* in_sizes, int n_in,
                              void* d_out, int out_size) {
    const float* feat   = (const float*)d_in[0];
    const void*  src    = d_in[1];
    const void*  dst    = d_in[2];
    const float* Wself  = (const float*)d_in[3];
    const float* Wneigh = (const float*)d_in[4];
    const float* bneigh = (const float*)d_in[5];
    const float* Wfc    = (const float*)d_in[6];
    const float* bfc    = (const float*)d_in[7];
    float*       out    = (float*)d_out;
    int E = in_sizes[1];

    cudaFuncSetAttribute(mma_gemm_kernel,
                         cudaFuncAttributeMaxDynamicSharedMemorySize, SMEM_TOTAL);

    prep_fill_kernel<<<1024, 256>>>(feat, src, dst, E);
    aggregate_kernel<<<(N_NODES * 32 + 255) / 256, 256>>>();
    mma_gemm_kernel<<<148, 512, SMEM_TOTAL>>>(
        Wself, Wneigh, bneigh, Wfc, bfc, out);
}